// round 5
// baseline (speedup 1.0000x reference)
#include <cuda_runtime.h>
#include <cstdint>

// RandomSaltPepper — bit-exact JAX threefry (partitionable path).
// R3: rotations moved off the alu pipe. rotl(x,r) is computed as
// mul.wide.u32(x, 2^r) -> (lo = x<<r, hi = x>>(32-r)) on the FMA pipe, and the
// round's xor becomes ONE LOP3: (lo | hi) ^ x0. Per round: alu ops 2 -> 1.
// Rotation multipliers are runtime kernel args so ptxas cannot turn them back
// into SHF. Adds remain forced onto the fma pipe via mad.lo.u32 with runtime 1.

struct TFParams {
    // keys: [0]=k0 [1]=k1 [2]=ks2 [3]=ks2+1 [4]=k0+2 [5]=k1+3 [6]=ks2+4 [7]=k0+5 (mask)
    //       [8..15] same layout (color)
    uint32_t k[16];
    // mult[i] = 1u << r for r in {13,15,26,6,17,29,16,24}
    uint32_t mult[8];
};

// add on the fma pipe: r = a*one + b (one == 1 at runtime)
__device__ __forceinline__ uint32_t madd(uint32_t a, uint32_t one, uint32_t b) {
    uint32_t r;
    asm("mad.lo.u32 %0, %1, %2, %3;" : "=r"(r) : "r"(a), "r"(one), "r"(b));
    return r;
}

// one threefry round: x0 += x1; x1 = rotl(x1, r) ^ x0
// rotl via wide multiply (fma pipe) + single LOP3 (alu pipe)
__device__ __forceinline__ void tf_round(uint32_t& x0, uint32_t& x1,
                                         uint32_t mult, uint32_t one) {
    x0 = madd(x1, one, x0);                                     // IMAD (fma)
    unsigned long long w = (unsigned long long)x1 * mult;       // IMAD.WIDE (fma)
    uint32_t lo = (uint32_t)w;
    uint32_t hi = (uint32_t)(w >> 32);
    x1 = (lo | hi) ^ x0;                                        // single LOP3 (alu)
}

// threefry2x32, counter = (0, ctr), returns o0 ^ o1
__device__ __forceinline__ uint32_t tf_xor(const uint32_t* __restrict__ K,
                                           const uint32_t* __restrict__ M,
                                           uint32_t ctr, uint32_t one) {
    uint32_t x0 = K[0];
    uint32_t x1 = madd(ctr, one, K[1]);
    tf_round(x0,x1,M[0],one); tf_round(x0,x1,M[1],one); tf_round(x0,x1,M[2],one); tf_round(x0,x1,M[3],one);
    x0 = madd(K[1], one, x0);  x1 = madd(K[3], one, x1);   // += k1, += ks2+1
    tf_round(x0,x1,M[4],one); tf_round(x0,x1,M[5],one); tf_round(x0,x1,M[6],one); tf_round(x0,x1,M[7],one);
    x0 = madd(K[2], one, x0);  x1 = madd(K[4], one, x1);   // += ks2, += k0+2
    tf_round(x0,x1,M[0],one); tf_round(x0,x1,M[1],one); tf_round(x0,x1,M[2],one); tf_round(x0,x1,M[3],one);
    x0 = madd(K[0], one, x0);  x1 = madd(K[5], one, x1);   // += k0,  += k1+3
    tf_round(x0,x1,M[4],one); tf_round(x0,x1,M[5],one); tf_round(x0,x1,M[6],one); tf_round(x0,x1,M[7],one);
    x0 = madd(K[1], one, x0);  x1 = madd(K[6], one, x1);   // += k1,  += ks2+4
    tf_round(x0,x1,M[0],one); tf_round(x0,x1,M[1],one); tf_round(x0,x1,M[2],one); tf_round(x0,x1,M[3],one);
    x0 = madd(K[2], one, x0);  x1 = madd(K[7], one, x1);   // += ks2, += k0+5
    return x0 ^ x1;
}

// ---------------- host threefry2x32 (key derivation) ----------------
static void tf_round_h(uint32_t& x0, uint32_t& x1, int r) {
    x0 += x1;
    x1 = (x1 << r) | (x1 >> (32 - r));
    x1 ^= x0;
}
static void tf_host(uint32_t k0, uint32_t k1, uint32_t x0in, uint32_t x1in,
                    uint32_t& o0, uint32_t& o1) {
    uint32_t ks2 = k0 ^ k1 ^ 0x1BD11BDAu;
    uint32_t x0 = x0in + k0;
    uint32_t x1 = x1in + k1;
    tf_round_h(x0,x1,13); tf_round_h(x0,x1,15); tf_round_h(x0,x1,26); tf_round_h(x0,x1, 6);
    x0 += k1;  x1 += ks2 + 1u;
    tf_round_h(x0,x1,17); tf_round_h(x0,x1,29); tf_round_h(x0,x1,16); tf_round_h(x0,x1,24);
    x0 += ks2; x1 += k0 + 2u;
    tf_round_h(x0,x1,13); tf_round_h(x0,x1,15); tf_round_h(x0,x1,26); tf_round_h(x0,x1, 6);
    x0 += k0;  x1 += k1 + 3u;
    tf_round_h(x0,x1,17); tf_round_h(x0,x1,29); tf_round_h(x0,x1,16); tf_round_h(x0,x1,24);
    x0 += k1;  x1 += ks2 + 4u;
    tf_round_h(x0,x1,13); tf_round_h(x0,x1,15); tf_round_h(x0,x1,26); tf_round_h(x0,x1, 6);
    x0 += ks2; x1 += k0 + 5u;
    o0 = x0; o1 = x1;
}

// ---------------- kernel ----------------
// B=64, C=3, H=W=512. HW = 2^18, positions P = 2^24. 4 consecutive positions/thread.
__global__ __launch_bounds__(256)
void RandomSaltPepper_9380208574641_kernel(
    const float4* __restrict__ in, float4* __restrict__ out,
    TFParams prm, uint32_t one)
{
    const uint32_t* __restrict__ MK = prm.k;       // mask key block
    const uint32_t* __restrict__ CK = prm.k + 8;   // color key block
    const uint32_t* __restrict__ M  = prm.mult;    // rotation multipliers (runtime)

    uint32_t t  = blockIdx.x * blockDim.x + threadIdx.x;   // 0 .. 2^22-1
    uint32_t p0 = t << 2;                                  // base (b,h,w) index
    uint32_t b  = p0 >> 18;                                // batch
    uint32_t q4 = (p0 & 0x3FFFFu) >> 2;                    // float4 index within HW

    // hoist loads — latency hides under ~600 ALU/FMA instructions below
    uint32_t i0 = ((b * 3u + 0u) << 16) + q4;
    uint32_t i1 = i0 + (1u << 16);
    uint32_t i2 = i0 + (2u << 16);
    float4 v0 = in[i0];
    float4 v1 = in[i1];
    float4 v2 = in[i2];

    bool  m[4];
    float col[4];
#pragma unroll
    for (int i = 0; i < 4; i++) {
        uint32_t bu = tf_xor(MK, M, p0 + i, one);
        m[i] = (bu & 0x80000000u) == 0u;                   // uniform < 0.5
        uint32_t bc = tf_xor(CK, M, p0 + i, one);
        col[i] = (bc & 1u) ? 0.0f : 1.0f;                  // 0 -> salt(1), 1 -> pepper(0)
    }

    float4 o0, o1, o2;
    o0.x = m[0] ? col[0] : v0.x;  o0.y = m[1] ? col[1] : v0.y;
    o0.z = m[2] ? col[2] : v0.z;  o0.w = m[3] ? col[3] : v0.w;
    o1.x = m[0] ? col[0] : v1.x;  o1.y = m[1] ? col[1] : v1.y;
    o1.z = m[2] ? col[2] : v1.z;  o1.w = m[3] ? col[3] : v1.w;
    o2.x = m[0] ? col[0] : v2.x;  o2.y = m[1] ? col[1] : v2.y;
    o2.z = m[2] ? col[2] : v2.z;  o2.w = m[3] ? col[3] : v2.w;
    out[i0] = o0;
    out[i1] = o1;
    out[i2] = o2;
}

extern "C" void kernel_launch(void* const* d_in, const int* in_sizes, int n_in,
                              void* d_out, int out_size)
{
    const float4* in  = (const float4*)d_in[0];
    float4*       out = (float4*)d_out;

    // ---- derive JAX keys on host ----
    uint32_t k1a, k1b, k2a, k2b;
    tf_host(0u, 42u, 0u, 0u, k1a, k1b);          // k1 = split(root)[0]
    tf_host(0u, 42u, 0u, 1u, k2a, k2b);          // k2 = split(root)[1]
    uint32_t kb0, kb1;
    tf_host(k2a, k2b, 0u, 1u, kb0, kb1);         // randint internal split, child 1

    TFParams prm;
    {
        uint32_t k0 = k1a, k1 = k1b, ks2 = k0 ^ k1 ^ 0x1BD11BDAu;
        uint32_t* K = prm.k;
        K[0]=k0; K[1]=k1; K[2]=ks2; K[3]=ks2+1u; K[4]=k0+2u; K[5]=k1+3u; K[6]=ks2+4u; K[7]=k0+5u;
    }
    {
        uint32_t k0 = kb0, k1 = kb1, ks2 = k0 ^ k1 ^ 0x1BD11BDAu;
        uint32_t* K = prm.k + 8;
        K[0]=k0; K[1]=k1; K[2]=ks2; K[3]=ks2+1u; K[4]=k0+2u; K[5]=k1+3u; K[6]=ks2+4u; K[7]=k0+5u;
    }
    static const int rots[8] = {13, 15, 26, 6, 17, 29, 16, 24};
    for (int i = 0; i < 8; i++) prm.mult[i] = 1u << rots[i];

    const int threads = 256;
    const int blocks  = (1 << 22) / threads;     // 16384
    RandomSaltPepper_9380208574641_kernel<<<blocks, threads>>>(in, out, prm, 1u);
}

// round 6
// speedup vs baseline: 1.5668x; 1.5668x over previous
#include <cuda_runtime.h>
#include <cstdint>

// RandomSaltPepper — bit-exact JAX threefry (partitionable path).
// R5: revert R3's wide-mul rotate (reg-pair pressure killed ILP). Keep R2 core
// (IMAD adds on fma pipe, SHF+LOP3 rotate on alu pipe). New:
//  - FFMA blend epilogue: out = fma(v, z, s), z/s floats built via IMAD — no SELs.
//  - mask bit extracted with umulhi(bu, two) on the fma pipe (two = runtime 2).
//  - __launch_bounds__(256,1): let ptxas use >32 regs so 8 TF chains stay live.

struct TFParams {
    // keys: [0]=k0 [1]=k1 [2]=ks2 [3]=ks2+1 [4]=k0+2 [5]=k1+3 [6]=ks2+4 [7]=k0+5 (mask)
    //       [8..15] same layout (color)
    uint32_t k[16];
};

// add forced onto the fma pipe: r = a*one + b (one == 1 at runtime)
__device__ __forceinline__ uint32_t madd(uint32_t a, uint32_t one, uint32_t b) {
    uint32_t r;
    asm("mad.lo.u32 %0, %1, %2, %3;" : "=r"(r) : "r"(a), "r"(one), "r"(b));
    return r;
}

__device__ __forceinline__ void tf_round(uint32_t& x0, uint32_t& x1, int r, uint32_t one) {
    x0 = madd(x1, one, x0);                       // IMAD  (fma pipe)
    x1 = __funnelshift_l(x1, x1, r) ^ x0;         // SHF + LOP3 (alu pipe)
}

// threefry2x32, counter = (0, ctr), returns o0 ^ o1
__device__ __forceinline__ uint32_t tf_xor(const uint32_t* __restrict__ K,
                                           uint32_t ctr, uint32_t one) {
    uint32_t x0 = K[0];
    uint32_t x1 = madd(ctr, one, K[1]);
    tf_round(x0,x1,13,one); tf_round(x0,x1,15,one); tf_round(x0,x1,26,one); tf_round(x0,x1, 6,one);
    x0 = madd(K[1], one, x0);  x1 = madd(K[3], one, x1);   // += k1, += ks2+1
    tf_round(x0,x1,17,one); tf_round(x0,x1,29,one); tf_round(x0,x1,16,one); tf_round(x0,x1,24,one);
    x0 = madd(K[2], one, x0);  x1 = madd(K[4], one, x1);   // += ks2, += k0+2
    tf_round(x0,x1,13,one); tf_round(x0,x1,15,one); tf_round(x0,x1,26,one); tf_round(x0,x1, 6,one);
    x0 = madd(K[0], one, x0);  x1 = madd(K[5], one, x1);   // += k0,  += k1+3
    tf_round(x0,x1,17,one); tf_round(x0,x1,29,one); tf_round(x0,x1,16,one); tf_round(x0,x1,24,one);
    x0 = madd(K[1], one, x0);  x1 = madd(K[6], one, x1);   // += k1,  += ks2+4
    tf_round(x0,x1,13,one); tf_round(x0,x1,15,one); tf_round(x0,x1,26,one); tf_round(x0,x1, 6,one);
    x0 = madd(K[2], one, x0);  x1 = madd(K[7], one, x1);   // += ks2, += k0+5
    return x0 ^ x1;
}

// ---------------- host threefry2x32 (key derivation) ----------------
static void tf_round_h(uint32_t& x0, uint32_t& x1, int r) {
    x0 += x1;
    x1 = (x1 << r) | (x1 >> (32 - r));
    x1 ^= x0;
}
static void tf_host(uint32_t k0, uint32_t k1, uint32_t x0in, uint32_t x1in,
                    uint32_t& o0, uint32_t& o1) {
    uint32_t ks2 = k0 ^ k1 ^ 0x1BD11BDAu;
    uint32_t x0 = x0in + k0;
    uint32_t x1 = x1in + k1;
    tf_round_h(x0,x1,13); tf_round_h(x0,x1,15); tf_round_h(x0,x1,26); tf_round_h(x0,x1, 6);
    x0 += k1;  x1 += ks2 + 1u;
    tf_round_h(x0,x1,17); tf_round_h(x0,x1,29); tf_round_h(x0,x1,16); tf_round_h(x0,x1,24);
    x0 += ks2; x1 += k0 + 2u;
    tf_round_h(x0,x1,13); tf_round_h(x0,x1,15); tf_round_h(x0,x1,26); tf_round_h(x0,x1, 6);
    x0 += k0;  x1 += k1 + 3u;
    tf_round_h(x0,x1,17); tf_round_h(x0,x1,29); tf_round_h(x0,x1,16); tf_round_h(x0,x1,24);
    x0 += k1;  x1 += ks2 + 4u;
    tf_round_h(x0,x1,13); tf_round_h(x0,x1,15); tf_round_h(x0,x1,26); tf_round_h(x0,x1, 6);
    x0 += ks2; x1 += k0 + 5u;
    o0 = x0; o1 = x1;
}

// ---------------- kernel ----------------
// B=64, C=3, H=W=512. HW = 2^18, positions P = 2^24. 4 consecutive positions/thread.
__global__ __launch_bounds__(256, 1)
void RandomSaltPepper_9380208574641_kernel(
    const float4* __restrict__ in, float4* __restrict__ out,
    TFParams prm, uint32_t one, uint32_t two, uint32_t fone)
{
    const uint32_t* __restrict__ MK = prm.k;       // mask key block
    const uint32_t* __restrict__ CK = prm.k + 8;   // color key block

    uint32_t t  = blockIdx.x * blockDim.x + threadIdx.x;   // 0 .. 2^22-1
    uint32_t p0 = t << 2;                                  // base (b,h,w) index
    uint32_t b  = p0 >> 18;                                // batch
    uint32_t q4 = (p0 & 0x3FFFFu) >> 2;                    // float4 index within HW

    // hoist loads — latency hides under ~570 ALU/FMA instructions below
    uint32_t i0 = ((b * 3u + 0u) << 16) + q4;
    uint32_t i1 = i0 + (1u << 16);
    uint32_t i2 = i0 + (2u << 16);
    float4 v0 = in[i0];
    float4 v1 = in[i1];
    float4 v2 = in[i2];

    // z[i] = 1.0f if position keeps the image (mask false), else 0.0f
    // s[i] = 1.0f if masked AND salt, else 0.0f            out = v*z + s
    float z[4], s[4];
#pragma unroll
    for (int i = 0; i < 4; i++) {
        uint32_t bu = tf_xor(MK, p0 + i, one);
        uint32_t bc = tf_xor(CK, p0 + i, one);
        uint32_t tb = __umulhi(bu, two);               // bit31(bu): 1 = keep image (fma pipe)
        uint32_t sb = (~tb) & (~bc) & 1u;              // masked & salt      (one LOP3, alu)
        z[i] = __uint_as_float(tb * fone);             // IMAD (fma): 0x3F800000 or 0
        s[i] = __uint_as_float(sb * fone);             // IMAD (fma)
    }

    float4 o0, o1, o2;
    o0.x = fmaf(v0.x, z[0], s[0]);  o0.y = fmaf(v0.y, z[1], s[1]);
    o0.z = fmaf(v0.z, z[2], s[2]);  o0.w = fmaf(v0.w, z[3], s[3]);
    o1.x = fmaf(v1.x, z[0], s[0]);  o1.y = fmaf(v1.y, z[1], s[1]);
    o1.z = fmaf(v1.z, z[2], s[2]);  o1.w = fmaf(v1.w, z[3], s[3]);
    o2.x = fmaf(v2.x, z[0], s[0]);  o2.y = fmaf(v2.y, z[1], s[1]);
    o2.z = fmaf(v2.z, z[2], s[2]);  o2.w = fmaf(v2.w, z[3], s[3]);
    out[i0] = o0;
    out[i1] = o1;
    out[i2] = o2;
}

extern "C" void kernel_launch(void* const* d_in, const int* in_sizes, int n_in,
                              void* d_out, int out_size)
{
    const float4* in  = (const float4*)d_in[0];
    float4*       out = (float4*)d_out;

    // ---- derive JAX keys on host ----
    uint32_t k1a, k1b, k2a, k2b;
    tf_host(0u, 42u, 0u, 0u, k1a, k1b);          // k1 = split(root)[0]
    tf_host(0u, 42u, 0u, 1u, k2a, k2b);          // k2 = split(root)[1]
    uint32_t kb0, kb1;
    tf_host(k2a, k2b, 0u, 1u, kb0, kb1);         // randint internal split, child 1

    TFParams prm;
    {
        uint32_t k0 = k1a, k1 = k1b, ks2 = k0 ^ k1 ^ 0x1BD11BDAu;
        uint32_t* K = prm.k;
        K[0]=k0; K[1]=k1; K[2]=ks2; K[3]=ks2+1u; K[4]=k0+2u; K[5]=k1+3u; K[6]=ks2+4u; K[7]=k0+5u;
    }
    {
        uint32_t k0 = kb0, k1 = kb1, ks2 = k0 ^ k1 ^ 0x1BD11BDAu;
        uint32_t* K = prm.k + 8;
        K[0]=k0; K[1]=k1; K[2]=ks2; K[3]=ks2+1u; K[4]=k0+2u; K[5]=k1+3u; K[6]=ks2+4u; K[7]=k0+5u;
    }

    const int threads = 256;
    const int blocks  = (1 << 22) / threads;     // 16384
    RandomSaltPepper_9380208574641_kernel<<<blocks, threads>>>(
        in, out, prm, 1u, 2u, 0x3F800000u);
}